// round 5
// baseline (speedup 1.0000x reference)
#include <cuda_runtime.h>
#include <cuda_bf16.h>
#include <math.h>
#include <stdint.h>

// Problem dims (fixed)
#define B_  4
#define S_  1024
#define D_  1024
#define H_  512
#define N_  32
#define BS_ 4096
#define H2_ 1024

// ---------------------------------------------------------------------------
// Scratch (__device__ globals; no cudaMalloc allowed)
// ---------------------------------------------------------------------------
__device__ __align__(256) __nv_bfloat16 g_Qhi[BS_ * D_];
__device__ __align__(256) __nv_bfloat16 g_Qlo[BS_ * D_];
__device__ __align__(256) __nv_bfloat16 g_W1Thi[H2_ * D_];  // [n][k]
__device__ __align__(256) __nv_bfloat16 g_W1Tlo[H2_ * D_];
__device__ __align__(256) __nv_bfloat16 g_W2Thi[H_ * H2_];  // [n][k]
__device__ __align__(256) __nv_bfloat16 g_W2Tlo[H_ * H2_];
__device__ __align__(256) __nv_bfloat16 g_hhi[BS_ * H2_];
__device__ __align__(256) __nv_bfloat16 g_hlo[BS_ * H2_];
__device__ __align__(256) float g_A[B_ * N_ * H_];

// ---------------------------------------------------------------------------
// Helpers (plain sm_80-level ISA only)
// ---------------------------------------------------------------------------
__device__ __forceinline__ uint32_t s2u(const void* p) {
    uint32_t a;
    asm("{ .reg .u64 t; cvta.to.shared.u64 t, %1; cvt.u32.u64 %0, t; }"
        : "=r"(a) : "l"(p));
    return a;
}
__device__ __forceinline__ void cp16(uint32_t dst, const void* src) {
    asm volatile("cp.async.cg.shared.global [%0], [%1], 16;"
                 :: "r"(dst), "l"(src));
}
#define CP_COMMIT() asm volatile("cp.async.commit_group;" ::: "memory")
#define CP_WAIT2()  asm volatile("cp.async.wait_group 2;" ::: "memory")

#define SW64(o) ((o) ^ (((o) >> 3) & 0x30))

__device__ __forceinline__ void ldsm4(uint32_t addr, uint32_t* r) {
    asm volatile("ldmatrix.sync.aligned.m8n8.x4.shared.b16 {%0,%1,%2,%3}, [%4];"
                 : "=r"(r[0]), "=r"(r[1]), "=r"(r[2]), "=r"(r[3]) : "r"(addr));
}
__device__ __forceinline__ void mma16816(float* c, const uint32_t* a,
                                         const uint32_t* b) {
    asm volatile(
        "mma.sync.aligned.m16n8k16.row.col.f32.bf16.bf16.f32 "
        "{%0,%1,%2,%3}, {%4,%5,%6,%7}, {%8,%9}, {%0,%1,%2,%3};"
        : "+f"(c[0]), "+f"(c[1]), "+f"(c[2]), "+f"(c[3])
        : "r"(a[0]), "r"(a[1]), "r"(a[2]), "r"(a[3]), "r"(b[0]), "r"(b[1]));
}

// ---------------------------------------------------------------------------
// Split fp32 -> bf16 hi/lo (row-major, same layout)
// ---------------------------------------------------------------------------
__global__ __launch_bounds__(256)
void split_plain(const float* __restrict__ X, __nv_bfloat16* __restrict__ hi,
                 __nv_bfloat16* __restrict__ lo)
{
    int idx = blockIdx.x * 256 + threadIdx.x;
    float4 v = reinterpret_cast<const float4*>(X)[idx];
    __nv_bfloat16 h[4], l[4];
    float* vp = &v.x;
    #pragma unroll
    for (int i = 0; i < 4; i++) {
        h[i] = __float2bfloat16(vp[i]);
        l[i] = __float2bfloat16(vp[i] - __bfloat162float(h[i]));
    }
    *reinterpret_cast<uint2*>(hi + (size_t)idx * 4) = *reinterpret_cast<uint2*>(h);
    *reinterpret_cast<uint2*>(lo + (size_t)idx * 4) = *reinterpret_cast<uint2*>(l);
}

// ---------------------------------------------------------------------------
// Transpose + split: W[K][Nn] fp32 -> hi/lo[Nn][K] bf16
// ---------------------------------------------------------------------------
__global__ __launch_bounds__(256)
void split_T(const float* __restrict__ W, __nv_bfloat16* __restrict__ hi,
             __nv_bfloat16* __restrict__ lo, int K, int Nn)
{
    __shared__ float t[32][33];
    int k0 = blockIdx.y * 32, n0 = blockIdx.x * 32;
    int tx = threadIdx.x & 31, ty = threadIdx.x >> 5;
    #pragma unroll
    for (int i = ty; i < 32; i += 8)
        t[i][tx] = W[(size_t)(k0 + i) * Nn + n0 + tx];
    __syncthreads();
    #pragma unroll
    for (int i = ty; i < 32; i += 8) {
        float v = t[tx][i];
        __nv_bfloat16 h = __float2bfloat16(v);
        __nv_bfloat16 l = __float2bfloat16(v - __bfloat162float(h));
        hi[(size_t)(n0 + i) * K + k0 + tx] = h;
        lo[(size_t)(n0 + i) * K + k0 + tx] = l;
    }
}

// ---------------------------------------------------------------------------
// bf16x3 mma.sync GEMM: C = Ahi*Bhi + Ahi*Blo + Alo*Bhi (+bias)
// A row-major [M,K] bf16, B row-major [Ntot,K] bf16 (pre-transposed).
// Warp grid NWM(m) x NWN(n); each warp computes a 64m x 64n tile
// (mt=4, nt=8). BM = 64*NWM, BN = 64*NWN, BK=32, 4-stage cp.async.
// ---------------------------------------------------------------------------
template<int NWM, int NWN, bool GELU_SPLIT>
__global__ __launch_bounds__(NWM * NWN * 32)
void gemm_mma3(const __nv_bfloat16* __restrict__ Ahi0,
               const __nv_bfloat16* __restrict__ Alo0,
               const __nv_bfloat16* __restrict__ Bhi0,
               const __nv_bfloat16* __restrict__ Blo0,
               const float* __restrict__ bias,
               float* __restrict__ Cf,
               __nv_bfloat16* __restrict__ Chi,
               __nv_bfloat16* __restrict__ Clo,
               int K, int Ntot)
{
    constexpr int BM = 64 * NWM, BN = 64 * NWN, BK = 32, STG = 4;
    constexpr int T = NWM * NWN * 32;
    constexpr int STAGE_BYTES = (BM + BN) * BK * 2;
    extern __shared__ __align__(128) char smem[];
    const uint32_t sb = s2u(smem);

    const int tid = threadIdx.x;
    const int lane = tid & 31;
    const int wid = tid >> 5;
    const int wm = wid % NWM;        // warp row: 64 m-rows
    const int wn = wid / NWM;        // warp col: 64 n-cols

    const int rowBase = blockIdx.y * BM;
    const int colBase = blockIdx.x * BN;

    const int KSEG = K / BK;
    const int KT = 3 * KSEG;
    const __nv_bfloat16* Asrc[3] = {Ahi0, Ahi0, Alo0};
    const __nv_bfloat16* Bsrc[3] = {Bhi0, Blo0, Bhi0};

    auto load_stage = [&](int kt) {
        int seg = kt / KSEG, kk = kt - seg * KSEG;
        const __nv_bfloat16* Ag = Asrc[seg];
        const __nv_bfloat16* Bg = Bsrc[seg];
        uint32_t st = sb + (kt & (STG - 1)) * STAGE_BYTES;
        #pragma unroll
        for (int i = 0; i < (BM * 4) / T; i++) {
            int idx = tid + i * T;
            int r = idx >> 2, c = idx & 3;
            cp16(st + SW64((uint32_t)(r * 64 + c * 16)),
                 Ag + (size_t)(rowBase + r) * K + kk * BK + c * 8);
        }
        uint32_t stB = st + BM * BK * 2;
        #pragma unroll
        for (int i = 0; i < (BN * 4) / T; i++) {
            int idx = tid + i * T;
            int r = idx >> 2, c = idx & 3;
            cp16(stB + SW64((uint32_t)(r * 64 + c * 16)),
                 Bg + (size_t)(colBase + r) * K + kk * BK + c * 8);
        }
        CP_COMMIT();
    };

    // ldmatrix offsets: A covers 64 m-rows (mt=4), B covers 64 n-cols (np=4)
    uint32_t offA[4][2];
    {
        int r = wm * 64 + (lane & 15);
        int c = (lane >> 4) * 16;
        #pragma unroll
        for (int mt = 0; mt < 4; mt++)
            #pragma unroll
            for (int k2 = 0; k2 < 2; k2++)
                offA[mt][k2] = SW64((uint32_t)((r + mt * 16) * 64 + k2 * 32 + c));
    }
    uint32_t offB[4][2];
    {
        int r = wn * 64 + (lane & 7) + ((lane >> 4) << 3);
        int c = ((lane >> 3) & 1) * 16;
        #pragma unroll
        for (int np = 0; np < 4; np++)
            #pragma unroll
            for (int k2 = 0; k2 < 2; k2++)
                offB[np][k2] = SW64((uint32_t)((r + np * 16) * 64 + k2 * 32 + c));
    }

    float acc[4][8][4];
    #pragma unroll
    for (int mt = 0; mt < 4; mt++)
        #pragma unroll
        for (int nt = 0; nt < 8; nt++)
            #pragma unroll
            for (int q = 0; q < 4; q++) acc[mt][nt][q] = 0.f;

    load_stage(0); load_stage(1); load_stage(2);

    for (int kt = 0; kt < KT; kt++) {
        CP_WAIT2();
        __syncthreads();
        if (kt + 3 < KT) load_stage(kt + 3);
        else CP_COMMIT();

        uint32_t st = sb + (kt & (STG - 1)) * STAGE_BYTES;
        uint32_t stB = st + BM * BK * 2;
        #pragma unroll
        for (int k2 = 0; k2 < 2; k2++) {
            uint32_t aF[4][4];
            #pragma unroll
            for (int mt = 0; mt < 4; mt++) ldsm4(st + offA[mt][k2], aF[mt]);
            #pragma unroll
            for (int nb = 0; nb < 2; nb++) {
                uint32_t bF[2][4];
                #pragma unroll
                for (int p = 0; p < 2; p++)
                    ldsm4(stB + offB[nb * 2 + p][k2], bF[p]);
                #pragma unroll
                for (int mt = 0; mt < 4; mt++)
                    #pragma unroll
                    for (int nn = 0; nn < 4; nn++)
                        mma16816(acc[mt][nb * 4 + nn], aF[mt],
                                 &bF[nn >> 1][(nn & 1) * 2]);
            }
        }
    }

    #pragma unroll
    for (int mt = 0; mt < 4; mt++) {
        #pragma unroll
        for (int nt = 0; nt < 8; nt++) {
            int gr = rowBase + wm * 64 + mt * 16 + (lane >> 2);
            int gc = colBase + wn * 64 + nt * 8 + 2 * (lane & 3);
            float b0 = bias[gc], b1 = bias[gc + 1];
            float v0 = acc[mt][nt][0] + b0, v1 = acc[mt][nt][1] + b1;
            float v2 = acc[mt][nt][2] + b0, v3 = acc[mt][nt][3] + b1;
            if (GELU_SPLIT) {
                float vv[4] = {v0, v1, v2, v3};
                __nv_bfloat16 hh[4], ll[4];
                #pragma unroll
                for (int q = 0; q < 4; q++) {
                    float g = 0.5f * vv[q] *
                              (1.0f + erff(vv[q] * 0.70710678118654752f));
                    hh[q] = __float2bfloat16(g);
                    ll[q] = __float2bfloat16(g - __bfloat162float(hh[q]));
                }
                *reinterpret_cast<uint32_t*>(Chi + (size_t)gr * Ntot + gc) =
                    *reinterpret_cast<uint32_t*>(hh);
                *reinterpret_cast<uint32_t*>(Clo + (size_t)gr * Ntot + gc) =
                    *reinterpret_cast<uint32_t*>(ll);
                *reinterpret_cast<uint32_t*>(Chi + (size_t)(gr + 8) * Ntot + gc) =
                    *reinterpret_cast<uint32_t*>(hh + 2);
                *reinterpret_cast<uint32_t*>(Clo + (size_t)(gr + 8) * Ntot + gc) =
                    *reinterpret_cast<uint32_t*>(ll + 2);
            } else {
                *reinterpret_cast<float2*>(Cf + (size_t)gr * Ntot + gc) =
                    make_float2(v0, v1);
                *reinterpret_cast<float2*>(Cf + (size_t)(gr + 8) * Ntot + gc) =
                    make_float2(v2, v3);
            }
        }
    }
}

// ---------------------------------------------------------------------------
// Row-wise L2 normalize in place
// ---------------------------------------------------------------------------
__global__ __launch_bounds__(128)
void normalize_rows(float* __restrict__ keys)
{
    __shared__ float red[4];
    int row = blockIdx.x;
    int t = threadIdx.x;
    float4* rp = reinterpret_cast<float4*>(keys + (size_t)row * H_);
    float4 v = rp[t];
    float ss = v.x * v.x + v.y * v.y + v.z * v.z + v.w * v.w;
    #pragma unroll
    for (int o = 16; o; o >>= 1) ss += __shfl_xor_sync(0xffffffffu, ss, o);
    if ((t & 31) == 0) red[t >> 5] = ss;
    __syncthreads();
    float total = red[0] + red[1] + red[2] + red[3];
    float scale = 1.0f / fmaxf(sqrtf(total), 1e-12f);
    v.x *= scale; v.y *= scale; v.z *= scale; v.w *= scale;
    rp[t] = v;
}

// ---------------------------------------------------------------------------
// A[b,n,i] = sum_j trace[b,n,(i+j) mod H] * Wa[j]
// ---------------------------------------------------------------------------
__global__ __launch_bounds__(512)
void corr_A2(const float* __restrict__ trace, const float* __restrict__ Wa,
             float* __restrict__ Aout)
{
    __shared__ float tr[H_];
    __shared__ float wa[H_];
    int bn = blockIdx.x;
    int t = threadIdx.x;
    tr[t] = trace[(size_t)bn * H_ + t];
    wa[t] = Wa[t];
    __syncthreads();
    float a = 0.f;
    #pragma unroll 8
    for (int j = 0; j < H_; j++)
        a = fmaf(wa[j], tr[(t + j) & (H_ - 1)], a);
    Aout[(size_t)bn * H_ + t] = a;
}

// ---------------------------------------------------------------------------
// Fused: scores -> softmax -> M -> circular correlation; 4 rows per block.
// ---------------------------------------------------------------------------
__global__ __launch_bounds__(256)
void fused_attn4(const float* __restrict__ keys, const float* __restrict__ trace,
                 const float* __restrict__ ba, float* __restrict__ context)
{
    __shared__ float key[4][H_];
    __shared__ float Mb[4][H_];
    __shared__ float sw[4][N_];

    int bs0 = blockIdx.x * 4;
    int b = bs0 >> 10;
    int tid = threadIdx.x, lane = tid & 31, w = tid >> 5;

    #pragma unroll
    for (int i = 0; i < 2; i++) {
        int idx = tid + i * 256;
        int r = idx >> 7, c = idx & 127;
        reinterpret_cast<float4*>(key[r])[c] =
            reinterpret_cast<const float4*>(keys + (size_t)(bs0 + r) * H_)[c];
    }
    __syncthreads();

    const float* Ab = g_A + (size_t)b * N_ * H_;
    #pragma unroll
    for (int i = 0; i < 16; i++) {
        int p = w * 16 + i;
        int r = p >> 5, n = p & 31;
        const float4* Ar = reinterpret_cast<const float4*>(Ab + (size_t)n * H_);
        const float4* kk = reinterpret_cast<const float4*>(key[r]);
        float s = 0.f;
        #pragma unroll
        for (int c = 0; c < 4; c++) {
            float4 a4 = Ar[lane + c * 32];
            float4 k4 = kk[lane + c * 32];
            s += a4.x * k4.x + a4.y * k4.y + a4.z * k4.z + a4.w * k4.w;
        }
        #pragma unroll
        for (int o = 16; o; o >>= 1) s += __shfl_xor_sync(0xffffffffu, s, o);
        if (lane == 0) sw[r][n] = s;
    }
    __syncthreads();

    if (w < 4) {
        float s = sw[w][lane] + ba[0];
        float m = s;
        #pragma unroll
        for (int o = 16; o; o >>= 1) m = fmaxf(m, __shfl_xor_sync(0xffffffffu, m, o));
        float e = __expf(s - m);
        float sm = e;
        #pragma unroll
        for (int o = 16; o; o >>= 1) sm += __shfl_xor_sync(0xffffffffu, sm, o);
        sw[w][lane] = e / sm;
    }
    __syncthreads();

    const float* trb = trace + (size_t)b * N_ * H_;
    #pragma unroll
    for (int i = 0; i < 2; i++) {
        int idx = tid + i * 256;
        int r = idx >> 7, c = idx & 127;
        float4 acc = make_float4(0.f, 0.f, 0.f, 0.f);
        #pragma unroll
        for (int n = 0; n < N_; n++) {
            float wn = sw[r][n];
            float4 t4 = reinterpret_cast<const float4*>(trb + (size_t)n * H_)[c];
            acc.x = fmaf(wn, t4.x, acc.x);
            acc.y = fmaf(wn, t4.y, acc.y);
            acc.z = fmaf(wn, t4.z, acc.z);
            acc.w = fmaf(wn, t4.w, acc.w);
        }
        reinterpret_cast<float4*>(Mb[r])[c] = acc;
    }
    __syncthreads();

    {
        int r = tid >> 6;
        int h0 = (tid & 63) * 8;
        const float4* kp = reinterpret_cast<const float4*>(key[r]);
        const float4* mp = reinterpret_cast<const float4*>(Mb[r]);
        float acc[8];
        #pragma unroll
        for (int h = 0; h < 8; h++) acc[h] = 0.f;

        #pragma unroll 2
        for (int jc = 0; jc < 32; jc++) {
            int j = jc * 16;
            float kr[16];
            #pragma unroll
            for (int q = 0; q < 4; q++)
                *reinterpret_cast<float4*>(kr + 4 * q) = kp[(j >> 2) + q];
            float wv[24];
            int b4 = ((h0 + j) & (H_ - 1)) >> 2;
            #pragma unroll
            for (int q = 0; q < 6; q++)
                *reinterpret_cast<float4*>(wv + 4 * q) = mp[(b4 + q) & 127];
            #pragma unroll
            for (int t = 0; t < 16; t++)
                #pragma unroll
                for (int h = 0; h < 8; h++)
                    acc[h] = fmaf(kr[t], wv[t + h], acc[h]);
        }
        float* op = context + (size_t)(bs0 + r) * H_ + h0;
        *reinterpret_cast<float4*>(op) = make_float4(acc[0], acc[1], acc[2], acc[3]);
        *reinterpret_cast<float4*>(op + 4) = make_float4(acc[4], acc[5], acc[6], acc[7]);
    }
}

// ---------------------------------------------------------------------------
extern "C" void kernel_launch(void* const* d_in, const int* in_sizes, int n_in,
                              void* d_out, int out_size)
{
    const float* query = (const float*)d_in[0];
    const float* trace = (const float*)d_in[1];
    const float* W1    = (const float*)d_in[2];
    const float* b1    = (const float*)d_in[3];
    const float* W2    = (const float*)d_in[4];
    const float* b2    = (const float*)d_in[5];
    const float* Wa    = (const float*)d_in[6];
    const float* ba    = (const float*)d_in[7];

    float* context = (float*)d_out;
    float* keys    = (float*)d_out + (size_t)BS_ * H_;

    __nv_bfloat16 *Qhi, *Qlo, *W1Thi, *W1Tlo, *W2Thi, *W2Tlo, *hhi, *hlo;
    float* Abuf;
    cudaGetSymbolAddress((void**)&Qhi, g_Qhi);
    cudaGetSymbolAddress((void**)&Qlo, g_Qlo);
    cudaGetSymbolAddress((void**)&W1Thi, g_W1Thi);
    cudaGetSymbolAddress((void**)&W1Tlo, g_W1Tlo);
    cudaGetSymbolAddress((void**)&W2Thi, g_W2Thi);
    cudaGetSymbolAddress((void**)&W2Tlo, g_W2Tlo);
    cudaGetSymbolAddress((void**)&hhi, g_hhi);
    cudaGetSymbolAddress((void**)&hlo, g_hlo);
    cudaGetSymbolAddress((void**)&Abuf, g_A);

    // GEMM1: NWM=4, NWN=2 -> BM=256, BN=128, 256 threads, 96 KB smem
    const int SMEM1 = 4 * (256 + 128) * 32 * 2;
    // GEMM2: NWM=2, NWN=2 -> BM=128, BN=128, 128 threads, 64 KB smem (2 CTA/SM)
    const int SMEM2 = 4 * (128 + 128) * 32 * 2;
    cudaFuncSetAttribute((const void*)gemm_mma3<4, 2, true>,
                         cudaFuncAttributeMaxDynamicSharedMemorySize, SMEM1);
    cudaFuncSetAttribute((const void*)gemm_mma3<2, 2, false>,
                         cudaFuncAttributeMaxDynamicSharedMemorySize, SMEM2);

    split_plain<<<(BS_ * D_ / 4) / 256, 256>>>(query, Qhi, Qlo);
    split_T<<<dim3(H2_ / 32, D_ / 32), 256>>>(W1, W1Thi, W1Tlo, D_, H2_);
    split_T<<<dim3(H_ / 32, H2_ / 32), 256>>>(W2, W2Thi, W2Tlo, H2_, H_);

    // GEMM1: h = gelu(Q @ W1 + b1) -> bf16 hi/lo. grid 8x16 = 128 CTAs.
    gemm_mma3<4, 2, true><<<dim3(H2_ / 128, BS_ / 256), 256, SMEM1>>>(
        Qhi, Qlo, W1Thi, W1Tlo, b1, nullptr, hhi, hlo, D_, H2_);

    // GEMM2: keys = h @ W2 + b2 -> fp32. grid 4x32 = 128 CTAs.
    gemm_mma3<2, 2, false><<<dim3(H_ / 128, BS_ / 128), 128, SMEM2>>>(
        hhi, hlo, W2Thi, W2Tlo, b2, keys, nullptr, nullptr, H2_, H_);

    normalize_rows<<<BS_, 128>>>(keys);
    corr_A2<<<B_ * N_, 512>>>(trace, Wa, Abuf);
    fused_attn4<<<BS_ / 4, 256>>>(keys, trace, ba, context);
}

// round 6
// speedup vs baseline: 1.1446x; 1.1446x over previous
#include <cuda_runtime.h>
#include <cuda_bf16.h>
#include <math.h>
#include <stdint.h>

// Problem dims (fixed)
#define B_  4
#define S_  1024
#define D_  1024
#define H_  512
#define N_  32
#define BS_ 4096
#define H2_ 1024

// ---------------------------------------------------------------------------
// Scratch (__device__ globals; no cudaMalloc allowed)
// ---------------------------------------------------------------------------
__device__ __align__(256) __nv_bfloat16 g_Qhi[BS_ * D_];
__device__ __align__(256) __nv_bfloat16 g_Qlo[BS_ * D_];
__device__ __align__(256) __nv_bfloat16 g_W1Thi[H2_ * D_];  // [n][k]
__device__ __align__(256) __nv_bfloat16 g_W1Tlo[H2_ * D_];
__device__ __align__(256) __nv_bfloat16 g_W2Thi[H_ * H2_];  // [n][k]
__device__ __align__(256) __nv_bfloat16 g_W2Tlo[H_ * H2_];
__device__ __align__(256) __nv_bfloat16 g_hhi[BS_ * H2_];
__device__ __align__(256) __nv_bfloat16 g_hlo[BS_ * H2_];
__device__ __align__(256) float g_A[B_ * N_ * H_];

// ---------------------------------------------------------------------------
// Helpers (plain sm_80-level ISA only)
// ---------------------------------------------------------------------------
__device__ __forceinline__ uint32_t s2u(const void* p) {
    uint32_t a;
    asm("{ .reg .u64 t; cvta.to.shared.u64 t, %1; cvt.u32.u64 %0, t; }"
        : "=r"(a) : "l"(p));
    return a;
}
__device__ __forceinline__ void cp16(uint32_t dst, const void* src) {
    asm volatile("cp.async.cg.shared.global [%0], [%1], 16;"
                 :: "r"(dst), "l"(src));
}
#define CP_COMMIT() asm volatile("cp.async.commit_group;" ::: "memory")
#define CP_WAIT2()  asm volatile("cp.async.wait_group 2;" ::: "memory")

#define SW64(o) ((o) ^ (((o) >> 3) & 0x30))

__device__ __forceinline__ void ldsm4(uint32_t addr, uint32_t* r) {
    asm volatile("ldmatrix.sync.aligned.m8n8.x4.shared.b16 {%0,%1,%2,%3}, [%4];"
                 : "=r"(r[0]), "=r"(r[1]), "=r"(r[2]), "=r"(r[3]) : "r"(addr));
}
__device__ __forceinline__ void mma16816(float* c, const uint32_t* a,
                                         const uint32_t* b) {
    asm volatile(
        "mma.sync.aligned.m16n8k16.row.col.f32.bf16.bf16.f32 "
        "{%0,%1,%2,%3}, {%4,%5,%6,%7}, {%8,%9}, {%0,%1,%2,%3};"
        : "+f"(c[0]), "+f"(c[1]), "+f"(c[2]), "+f"(c[3])
        : "r"(a[0]), "r"(a[1]), "r"(a[2]), "r"(a[3]), "r"(b[0]), "r"(b[1]));
}

// ---------------------------------------------------------------------------
// Split fp32 -> bf16 hi/lo (row-major, same layout)
// ---------------------------------------------------------------------------
__global__ __launch_bounds__(256)
void split_plain(const float* __restrict__ X, __nv_bfloat16* __restrict__ hi,
                 __nv_bfloat16* __restrict__ lo)
{
    int idx = blockIdx.x * 256 + threadIdx.x;
    float4 v = reinterpret_cast<const float4*>(X)[idx];
    __nv_bfloat16 h[4], l[4];
    float* vp = &v.x;
    #pragma unroll
    for (int i = 0; i < 4; i++) {
        h[i] = __float2bfloat16(vp[i]);
        l[i] = __float2bfloat16(vp[i] - __bfloat162float(h[i]));
    }
    *reinterpret_cast<uint2*>(hi + (size_t)idx * 4) = *reinterpret_cast<uint2*>(h);
    *reinterpret_cast<uint2*>(lo + (size_t)idx * 4) = *reinterpret_cast<uint2*>(l);
}

// ---------------------------------------------------------------------------
// Transpose + split: W[K][Nn] fp32 -> hi/lo[Nn][K] bf16
// ---------------------------------------------------------------------------
__global__ __launch_bounds__(256)
void split_T(const float* __restrict__ W, __nv_bfloat16* __restrict__ hi,
             __nv_bfloat16* __restrict__ lo, int K, int Nn)
{
    __shared__ float t[32][33];
    int k0 = blockIdx.y * 32, n0 = blockIdx.x * 32;
    int tx = threadIdx.x & 31, ty = threadIdx.x >> 5;
    #pragma unroll
    for (int i = ty; i < 32; i += 8)
        t[i][tx] = W[(size_t)(k0 + i) * Nn + n0 + tx];
    __syncthreads();
    #pragma unroll
    for (int i = ty; i < 32; i += 8) {
        float v = t[tx][i];
        __nv_bfloat16 h = __float2bfloat16(v);
        __nv_bfloat16 l = __float2bfloat16(v - __bfloat162float(h));
        hi[(size_t)(n0 + i) * K + k0 + tx] = h;
        lo[(size_t)(n0 + i) * K + k0 + tx] = l;
    }
}

// ---------------------------------------------------------------------------
// bf16x3 mma.sync GEMM: C = Ahi*Bhi + Ahi*Blo + Alo*Bhi (+bias)
// A row-major [M,K] bf16, B row-major [Ntot,K] bf16 (pre-transposed).
// 4 warps (2m x 2n); each warp 32m x 64n (mt=2, nt=8).
// BM=64, BN=128, BK=32, 4-stage cp.async, 48 KB smem -> 4 CTAs/SM.
// ---------------------------------------------------------------------------
template<bool GELU_SPLIT>
__global__ __launch_bounds__(128, 4)
void gemm_mma3(const __nv_bfloat16* __restrict__ Ahi0,
               const __nv_bfloat16* __restrict__ Alo0,
               const __nv_bfloat16* __restrict__ Bhi0,
               const __nv_bfloat16* __restrict__ Blo0,
               const float* __restrict__ bias,
               float* __restrict__ Cf,
               __nv_bfloat16* __restrict__ Chi,
               __nv_bfloat16* __restrict__ Clo,
               int K, int Ntot)
{
    constexpr int BM = 64, BN = 128, BK = 32, STG = 4;
    constexpr int T = 128;
    constexpr int STAGE_BYTES = (BM + BN) * BK * 2;   // 12 KB
    extern __shared__ __align__(128) char smem[];
    const uint32_t sb = s2u(smem);

    const int tid = threadIdx.x;
    const int lane = tid & 31;
    const int wid = tid >> 5;
    const int wm = wid & 1;          // warp row: 32 m-rows
    const int wn = wid >> 1;         // warp col: 64 n-cols

    const int rowBase = blockIdx.y * BM;
    const int colBase = blockIdx.x * BN;

    const int KSEG = K / BK;
    const int KT = 3 * KSEG;
    const __nv_bfloat16* Asrc[3] = {Ahi0, Ahi0, Alo0};
    const __nv_bfloat16* Bsrc[3] = {Bhi0, Blo0, Bhi0};

    auto load_stage = [&](int kt) {
        int seg = kt / KSEG, kk = kt - seg * KSEG;
        const __nv_bfloat16* Ag = Asrc[seg];
        const __nv_bfloat16* Bg = Bsrc[seg];
        uint32_t st = sb + (kt & (STG - 1)) * STAGE_BYTES;
        #pragma unroll
        for (int i = 0; i < (BM * 4) / T; i++) {   // 2
            int idx = tid + i * T;
            int r = idx >> 2, c = idx & 3;
            cp16(st + SW64((uint32_t)(r * 64 + c * 16)),
                 Ag + (size_t)(rowBase + r) * K + kk * BK + c * 8);
        }
        uint32_t stB = st + BM * BK * 2;
        #pragma unroll
        for (int i = 0; i < (BN * 4) / T; i++) {   // 4
            int idx = tid + i * T;
            int r = idx >> 2, c = idx & 3;
            cp16(stB + SW64((uint32_t)(r * 64 + c * 16)),
                 Bg + (size_t)(colBase + r) * K + kk * BK + c * 8);
        }
        CP_COMMIT();
    };

    uint32_t offA[2][2];
    {
        int r = wm * 32 + (lane & 15);
        int c = (lane >> 4) * 16;
        #pragma unroll
        for (int mt = 0; mt < 2; mt++)
            #pragma unroll
            for (int k2 = 0; k2 < 2; k2++)
                offA[mt][k2] = SW64((uint32_t)((r + mt * 16) * 64 + k2 * 32 + c));
    }
    uint32_t offB[4][2];
    {
        int r = wn * 64 + (lane & 7) + ((lane >> 4) << 3);
        int c = ((lane >> 3) & 1) * 16;
        #pragma unroll
        for (int np = 0; np < 4; np++)
            #pragma unroll
            for (int k2 = 0; k2 < 2; k2++)
                offB[np][k2] = SW64((uint32_t)((r + np * 16) * 64 + k2 * 32 + c));
    }

    float acc[2][8][4];
    #pragma unroll
    for (int mt = 0; mt < 2; mt++)
        #pragma unroll
        for (int nt = 0; nt < 8; nt++)
            #pragma unroll
            for (int q = 0; q < 4; q++) acc[mt][nt][q] = 0.f;

    load_stage(0); load_stage(1); load_stage(2);

    for (int kt = 0; kt < KT; kt++) {
        CP_WAIT2();
        __syncthreads();
        if (kt + 3 < KT) load_stage(kt + 3);
        else CP_COMMIT();

        uint32_t st = sb + (kt & (STG - 1)) * STAGE_BYTES;
        uint32_t stB = st + BM * BK * 2;
        #pragma unroll
        for (int k2 = 0; k2 < 2; k2++) {
            uint32_t aF[2][4], bF[4][4];
            #pragma unroll
            for (int mt = 0; mt < 2; mt++) ldsm4(st + offA[mt][k2], aF[mt]);
            #pragma unroll
            for (int np = 0; np < 4; np++) ldsm4(stB + offB[np][k2], bF[np]);
            #pragma unroll
            for (int mt = 0; mt < 2; mt++)
                #pragma unroll
                for (int nt = 0; nt < 8; nt++)
                    mma16816(acc[mt][nt], aF[mt], &bF[nt >> 1][(nt & 1) * 2]);
        }
    }

    #pragma unroll
    for (int mt = 0; mt < 2; mt++) {
        #pragma unroll
        for (int nt = 0; nt < 8; nt++) {
            int gr = rowBase + wm * 32 + mt * 16 + (lane >> 2);
            int gc = colBase + wn * 64 + nt * 8 + 2 * (lane & 3);
            float b0 = bias[gc], b1 = bias[gc + 1];
            float v0 = acc[mt][nt][0] + b0, v1 = acc[mt][nt][1] + b1;
            float v2 = acc[mt][nt][2] + b0, v3 = acc[mt][nt][3] + b1;
            if (GELU_SPLIT) {
                float vv[4] = {v0, v1, v2, v3};
                __nv_bfloat16 hh[4], ll[4];
                #pragma unroll
                for (int q = 0; q < 4; q++) {
                    float g = 0.5f * vv[q] *
                              (1.0f + erff(vv[q] * 0.70710678118654752f));
                    hh[q] = __float2bfloat16(g);
                    ll[q] = __float2bfloat16(g - __bfloat162float(hh[q]));
                }
                *reinterpret_cast<uint32_t*>(Chi + (size_t)gr * Ntot + gc) =
                    *reinterpret_cast<uint32_t*>(hh);
                *reinterpret_cast<uint32_t*>(Clo + (size_t)gr * Ntot + gc) =
                    *reinterpret_cast<uint32_t*>(ll);
                *reinterpret_cast<uint32_t*>(Chi + (size_t)(gr + 8) * Ntot + gc) =
                    *reinterpret_cast<uint32_t*>(hh + 2);
                *reinterpret_cast<uint32_t*>(Clo + (size_t)(gr + 8) * Ntot + gc) =
                    *reinterpret_cast<uint32_t*>(ll + 2);
            } else {
                *reinterpret_cast<float2*>(Cf + (size_t)gr * Ntot + gc) =
                    make_float2(v0, v1);
                *reinterpret_cast<float2*>(Cf + (size_t)(gr + 8) * Ntot + gc) =
                    make_float2(v2, v3);
            }
        }
    }
}

// ---------------------------------------------------------------------------
// Row-wise L2 normalize in place
// ---------------------------------------------------------------------------
__global__ __launch_bounds__(128)
void normalize_rows(float* __restrict__ keys)
{
    __shared__ float red[4];
    int row = blockIdx.x;
    int t = threadIdx.x;
    float4* rp = reinterpret_cast<float4*>(keys + (size_t)row * H_);
    float4 v = rp[t];
    float ss = v.x * v.x + v.y * v.y + v.z * v.z + v.w * v.w;
    #pragma unroll
    for (int o = 16; o; o >>= 1) ss += __shfl_xor_sync(0xffffffffu, ss, o);
    if ((t & 31) == 0) red[t >> 5] = ss;
    __syncthreads();
    float total = red[0] + red[1] + red[2] + red[3];
    float scale = 1.0f / fmaxf(sqrtf(total), 1e-12f);
    v.x *= scale; v.y *= scale; v.z *= scale; v.w *= scale;
    rp[t] = v;
}

// ---------------------------------------------------------------------------
// A[b,n,i] = sum_j trace[b,n,(i+j) mod H] * Wa[j]
// ---------------------------------------------------------------------------
__global__ __launch_bounds__(512)
void corr_A2(const float* __restrict__ trace, const float* __restrict__ Wa,
             float* __restrict__ Aout)
{
    __shared__ float tr[H_];
    __shared__ float wa[H_];
    int bn = blockIdx.x;
    int t = threadIdx.x;
    tr[t] = trace[(size_t)bn * H_ + t];
    wa[t] = Wa[t];
    __syncthreads();
    float a = 0.f;
    #pragma unroll 8
    for (int j = 0; j < H_; j++)
        a = fmaf(wa[j], tr[(t + j) & (H_ - 1)], a);
    Aout[(size_t)bn * H_ + t] = a;
}

// ---------------------------------------------------------------------------
// Fused: scores -> softmax -> M -> circular correlation; 4 rows per block.
// ---------------------------------------------------------------------------
__global__ __launch_bounds__(256)
void fused_attn4(const float* __restrict__ keys, const float* __restrict__ trace,
                 const float* __restrict__ ba, float* __restrict__ context)
{
    __shared__ float key[4][H_];
    __shared__ float Mb[4][H_];
    __shared__ float sw[4][N_];

    int bs0 = blockIdx.x * 4;
    int b = bs0 >> 10;
    int tid = threadIdx.x, lane = tid & 31, w = tid >> 5;

    #pragma unroll
    for (int i = 0; i < 2; i++) {
        int idx = tid + i * 256;
        int r = idx >> 7, c = idx & 127;
        reinterpret_cast<float4*>(key[r])[c] =
            reinterpret_cast<const float4*>(keys + (size_t)(bs0 + r) * H_)[c];
    }
    __syncthreads();

    const float* Ab = g_A + (size_t)b * N_ * H_;
    #pragma unroll
    for (int i = 0; i < 16; i++) {
        int p = w * 16 + i;
        int r = p >> 5, n = p & 31;
        const float4* Ar = reinterpret_cast<const float4*>(Ab + (size_t)n * H_);
        const float4* kk = reinterpret_cast<const float4*>(key[r]);
        float s = 0.f;
        #pragma unroll
        for (int c = 0; c < 4; c++) {
            float4 a4 = Ar[lane + c * 32];
            float4 k4 = kk[lane + c * 32];
            s += a4.x * k4.x + a4.y * k4.y + a4.z * k4.z + a4.w * k4.w;
        }
        #pragma unroll
        for (int o = 16; o; o >>= 1) s += __shfl_xor_sync(0xffffffffu, s, o);
        if (lane == 0) sw[r][n] = s;
    }
    __syncthreads();

    if (w < 4) {
        float s = sw[w][lane] + ba[0];
        float m = s;
        #pragma unroll
        for (int o = 16; o; o >>= 1) m = fmaxf(m, __shfl_xor_sync(0xffffffffu, m, o));
        float e = __expf(s - m);
        float sm = e;
        #pragma unroll
        for (int o = 16; o; o >>= 1) sm += __shfl_xor_sync(0xffffffffu, sm, o);
        sw[w][lane] = e / sm;
    }
    __syncthreads();

    const float* trb = trace + (size_t)b * N_ * H_;
    #pragma unroll
    for (int i = 0; i < 2; i++) {
        int idx = tid + i * 256;
        int r = idx >> 7, c = idx & 127;
        float4 acc = make_float4(0.f, 0.f, 0.f, 0.f);
        #pragma unroll
        for (int n = 0; n < N_; n++) {
            float wn = sw[r][n];
            float4 t4 = reinterpret_cast<const float4*>(trb + (size_t)n * H_)[c];
            acc.x = fmaf(wn, t4.x, acc.x);
            acc.y = fmaf(wn, t4.y, acc.y);
            acc.z = fmaf(wn, t4.z, acc.z);
            acc.w = fmaf(wn, t4.w, acc.w);
        }
        reinterpret_cast<float4*>(Mb[r])[c] = acc;
    }
    __syncthreads();

    {
        int r = tid >> 6;
        int h0 = (tid & 63) * 8;
        const float4* kp = reinterpret_cast<const float4*>(key[r]);
        const float4* mp = reinterpret_cast<const float4*>(Mb[r]);
        float acc[8];
        #pragma unroll
        for (int h = 0; h < 8; h++) acc[h] = 0.f;

        #pragma unroll 2
        for (int jc = 0; jc < 32; jc++) {
            int j = jc * 16;
            float kr[16];
            #pragma unroll
            for (int q = 0; q < 4; q++)
                *reinterpret_cast<float4*>(kr + 4 * q) = kp[(j >> 2) + q];
            float wv[24];
            int b4 = ((h0 + j) & (H_ - 1)) >> 2;
            #pragma unroll
            for (int q = 0; q < 6; q++)
                *reinterpret_cast<float4*>(wv + 4 * q) = mp[(b4 + q) & 127];
            #pragma unroll
            for (int t = 0; t < 16; t++)
                #pragma unroll
                for (int h = 0; h < 8; h++)
                    acc[h] = fmaf(kr[t], wv[t + h], acc[h]);
        }
        float* op = context + (size_t)(bs0 + r) * H_ + h0;
        *reinterpret_cast<float4*>(op) = make_float4(acc[0], acc[1], acc[2], acc[3]);
        *reinterpret_cast<float4*>(op + 4) = make_float4(acc[4], acc[5], acc[6], acc[7]);
    }
}

// ---------------------------------------------------------------------------
extern "C" void kernel_launch(void* const* d_in, const int* in_sizes, int n_in,
                              void* d_out, int out_size)
{
    const float* query = (const float*)d_in[0];
    const float* trace = (const float*)d_in[1];
    const float* W1    = (const float*)d_in[2];
    const float* b1    = (const float*)d_in[3];
    const float* W2    = (const float*)d_in[4];
    const float* b2    = (const float*)d_in[5];
    const float* Wa    = (const float*)d_in[6];
    const float* ba    = (const float*)d_in[7];

    float* context = (float*)d_out;
    float* keys    = (float*)d_out + (size_t)BS_ * H_;

    __nv_bfloat16 *Qhi, *Qlo, *W1Thi, *W1Tlo, *W2Thi, *W2Tlo, *hhi, *hlo;
    float* Abuf;
    cudaGetSymbolAddress((void**)&Qhi, g_Qhi);
    cudaGetSymbolAddress((void**)&Qlo, g_Qlo);
    cudaGetSymbolAddress((void**)&W1Thi, g_W1Thi);
    cudaGetSymbolAddress((void**)&W1Tlo, g_W1Tlo);
    cudaGetSymbolAddress((void**)&W2Thi, g_W2Thi);
    cudaGetSymbolAddress((void**)&W2Tlo, g_W2Tlo);
    cudaGetSymbolAddress((void**)&hhi, g_hhi);
    cudaGetSymbolAddress((void**)&hlo, g_hlo);
    cudaGetSymbolAddress((void**)&Abuf, g_A);

    // BM=64, BN=128, 4 stages: 48 KB
    const int SMEM = 4 * (64 + 128) * 32 * 2;
    cudaFuncSetAttribute((const void*)gemm_mma3<true>,
                         cudaFuncAttributeMaxDynamicSharedMemorySize, SMEM);
    cudaFuncSetAttribute((const void*)gemm_mma3<false>,
                         cudaFuncAttributeMaxDynamicSharedMemorySize, SMEM);

    split_plain<<<(BS_ * D_ / 4) / 256, 256>>>(query, Qhi, Qlo);
    split_T<<<dim3(H2_ / 32, D_ / 32), 256>>>(W1, W1Thi, W1Tlo, D_, H2_);
    split_T<<<dim3(H_ / 32, H2_ / 32), 256>>>(W2, W2Thi, W2Tlo, H2_, H_);

    // GEMM1: h = gelu(Q @ W1 + b1) -> bf16 hi/lo. grid 8x64 = 512 CTAs.
    gemm_mma3<true><<<dim3(H2_ / 128, BS_ / 64), 128, SMEM>>>(
        Qhi, Qlo, W1Thi, W1Tlo, b1, nullptr, hhi, hlo, D_, H2_);

    // GEMM2: keys = h @ W2 + b2 -> fp32. grid 4x64 = 256 CTAs.
    gemm_mma3<false><<<dim3(H_ / 128, BS_ / 64), 128, SMEM>>>(
        hhi, hlo, W2Thi, W2Tlo, b2, keys, nullptr, nullptr, H2_, H_);

    normalize_rows<<<BS_, 128>>>(keys);
    corr_A2<<<B_ * N_, 512>>>(trace, Wa, Abuf);
    fused_attn4<<<BS_ / 4, 256>>>(keys, trace, ba, context);
}